// round 15
// baseline (speedup 1.0000x reference)
#include <cuda_runtime.h>
#include <cuda_fp16.h>
#include <math.h>

#define D 128
#define NN 50000
#define NE 640000
#define MMPAD 132
#define KPAD 136   // halves per row in fp16 staging (128 + 8 pad)

// ---- scratch (device globals: allocation-free) ----
__device__ __half g_h0[NN * D];     // h0 (fp16)
__device__ __half g_short[NN * D];  // shortcut (fp16)
__device__ __half g_mean[NN * D];   // mean aggregation buffer (fp16)
__device__ __half g_t[NN * D];      // h1 (fp16)
__device__ __half g_w16[4][D * D];  // fp16 weights: dp_w, sc_w, g1_lw, g1_rw
__device__ __half g_w16b[2][D * D]; // fp16 weights: g2_lw, g2_rw
__device__ int    g_deg[NN];
__device__ int    g_cursor[NN];
__device__ int    g_rp[NN + 1];
__device__ int    g_col[NE];
__device__ unsigned long long g_desc[256];   // lookback descriptors
__device__ unsigned g_bar_arrive = 0;        // persistent-kernel barrier
__device__ unsigned g_bar_gen = 0;

// ---- host-side stream/event for forked graph capture (host objects, not device mem) ----
struct ForkCtx {
    cudaStream_t side;
    cudaEvent_t evFork, evJoin;
    ForkCtx() {
        cudaStreamCreateWithFlags(&side, cudaStreamNonBlocking);
        cudaEventCreateWithFlags(&evFork, cudaEventDisableTiming);
        cudaEventCreateWithFlags(&evJoin, cudaEventDisableTiming);
    }
};
static ForkCtx g_fork;

__device__ __forceinline__ float gelu_f(float x) {
    return 0.5f * x * (1.0f + erff(x * 0.70710678118654752f));
}

__device__ __forceinline__ unsigned f2h2(float a, float b) {
    __half2 h = __floats2half2_rn(a, b);
    return *(unsigned*)&h;
}

__device__ __forceinline__ void mma_f16(float* c, const unsigned* a, const unsigned* b) {
    asm volatile(
        "mma.sync.aligned.m16n8k16.row.col.f32.f16.f16.f32 "
        "{%0,%1,%2,%3},{%4,%5,%6,%7},{%8,%9},{%0,%1,%2,%3};"
        : "+f"(c[0]), "+f"(c[1]), "+f"(c[2]), "+f"(c[3])
        : "r"(a[0]), "r"(a[1]), "r"(a[2]), "r"(a[3]), "r"(b[0]), "r"(b[1]));
}

__device__ __forceinline__ void ldsm_x4(unsigned* r, unsigned addr) {
    asm volatile("ldmatrix.sync.aligned.m8n8.x4.shared.b16 {%0,%1,%2,%3}, [%4];"
        : "=r"(r[0]), "=r"(r[1]), "=r"(r[2]), "=r"(r[3]) : "r"(addr));
}

__device__ __forceinline__ unsigned ldsm_a_addr(const __half* as, int ar, int lane) {
    return (unsigned)__cvta_generic_to_shared(
        &as[(ar + (lane & 15)) * KPAD + ((lane >> 4) * 8)]);
}
__device__ __forceinline__ unsigned ldsm_b_addr(const __half* ws, int nb, int lane) {
    return (unsigned)__cvta_generic_to_shared(
        &ws[(nb + ((lane >> 4) * 8) + (lane & 7)) * KPAD + (((lane >> 3) & 1) * 8)]);
}

// ---- grid-wide barrier (all blocks guaranteed resident: launch_bounds(256,3), grid=SMs*3) ----
__device__ __forceinline__ void grid_barrier(int nblocks) {
    __syncthreads();
    if (threadIdx.x == 0) {
        __threadfence();
        unsigned gen = atomicAdd(&g_bar_gen, 0u);
        unsigned t = atomicAdd(&g_bar_arrive, 1u);
        if (t == (unsigned)nblocks - 1u) {
            g_bar_arrive = 0;
            __threadfence();
            atomicAdd(&g_bar_gen, 1u);
        } else {
            while (atomicAdd(&g_bar_gen, 0u) == gen) { }
        }
    }
    __syncthreads();
}

// ---------------- one-time weight fp32 -> fp16 conversion ----------------
__global__ void wconv_kernel(const float* __restrict__ w0, const float* __restrict__ w1,
                             const float* __restrict__ w2, const float* __restrict__ w3,
                             const float* __restrict__ w4, const float* __restrict__ w5) {
    int mat = blockIdx.x >> 5;
    int off = (((blockIdx.x & 31) * 256) + threadIdx.x) * 2;
    const float* src;
    __half* dst;
    switch (mat) {
        case 0:  src = w0; dst = g_w16[0];  break;
        case 1:  src = w1; dst = g_w16[1];  break;
        case 2:  src = w2; dst = g_w16[2];  break;
        case 3:  src = w3; dst = g_w16[3];  break;
        case 4:  src = w4; dst = g_w16b[0]; break;
        default: src = w5; dst = g_w16b[1]; break;
    }
    float2 v = *(const float2*)(src + off);
    *(unsigned*)(dst + off) = f2h2(v.x, v.y);
}

// ---------------- CSR build ----------------
__global__ void hist_kernel(const int* __restrict__ dst, int e_cnt) {
    int base = (blockIdx.x * blockDim.x + threadIdx.x) * 4;
    if (base + 4 <= e_cnt) {
        int4 d = *(const int4*)(dst + base);
        atomicAdd(&g_deg[d.x], 1);
        atomicAdd(&g_deg[d.y], 1);
        atomicAdd(&g_deg[d.z], 1);
        atomicAdd(&g_deg[d.w], 1);
    } else {
        for (int j = 0; j < 4; j++)
            if (base + j < e_cnt) atomicAdd(&g_deg[dst[base + j]], 1);
    }
}

__global__ void scan_lookback_kernel(int n) {
    __shared__ int wsum[8];
    __shared__ int s_total;
    __shared__ int s_excl;
    int tid = threadIdx.x, lane = tid & 31, wid = tid >> 5;
    int bid = blockIdx.x;
    int i = bid * 256 + tid;
    int v = (i < n) ? g_deg[i] : 0;
    int x = v;
    #pragma unroll
    for (int off = 1; off < 32; off <<= 1) {
        int t = __shfl_up_sync(0xFFFFFFFFu, x, off);
        if (lane >= off) x += t;
    }
    if (lane == 31) wsum[wid] = x;
    __syncthreads();
    if (tid < 32) {
        int w = (tid < 8) ? wsum[tid] : 0;
        #pragma unroll
        for (int off = 1; off < 8; off <<= 1) {
            int t = __shfl_up_sync(0xFFFFFFFFu, w, off);
            if (tid >= off) w += t;
        }
        if (tid < 8) wsum[tid] = w;
    }
    __syncthreads();
    int incl = x + ((wid > 0) ? wsum[wid - 1] : 0);
    if (tid == 255) { s_total = incl; }
    __syncthreads();
    int total = s_total;

    if (tid == 0) {
        __threadfence();
        unsigned long long st = (bid == 0) ? (2ULL << 32) : (1ULL << 32);
        atomicExch(&g_desc[bid], st | (unsigned)total);
        if (bid == 0) s_excl = 0;
    }
    if (bid > 0 && wid == 0) {
        int j = bid - 1 - lane;
        long ex = 0;
        while (true) {
            unsigned long long d;
            unsigned st;
            if (j >= 0) {
                do { d = atomicAdd(&g_desc[j], 0ULL); st = (unsigned)(d >> 32); } while (st == 0);
            } else {
                d = (2ULL << 32); st = 2u;
            }
            unsigned mask = __ballot_sync(0xFFFFFFFFu, st == 2u);
            if (mask) {
                int firstP = __ffs(mask) - 1;
                unsigned contrib = (lane <= firstP) ? (unsigned)d : 0u;
                #pragma unroll
                for (int off = 16; off; off >>= 1)
                    contrib += __shfl_xor_sync(0xFFFFFFFFu, contrib, off);
                ex += (long)contrib;
                break;
            } else {
                unsigned contrib = (unsigned)d;
                #pragma unroll
                for (int off = 16; off; off >>= 1)
                    contrib += __shfl_xor_sync(0xFFFFFFFFu, contrib, off);
                ex += (long)contrib;
                j -= 32;
            }
        }
        if (lane == 0) {
            __threadfence();
            atomicExch(&g_desc[bid], (2ULL << 32) | (unsigned)(ex + total));
            s_excl = (int)ex;
        }
    }
    __syncthreads();
    int off = s_excl;
    if (i < n) {
        int gincl = incl + off;
        g_rp[i + 1] = gincl;
        g_cursor[i] = gincl - v;
    }
    if (i == 0) g_rp[0] = 0;
}

__global__ void fill_kernel(const int* __restrict__ src, const int* __restrict__ dst, int e_cnt) {
    int base = (blockIdx.x * blockDim.x + threadIdx.x) * 4;
    if (base + 4 <= e_cnt) {
        int4 s = *(const int4*)(src + base);
        int4 d = *(const int4*)(dst + base);
        g_col[atomicAdd(&g_cursor[d.x], 1)] = s.x;
        g_col[atomicAdd(&g_cursor[d.y], 1)] = s.y;
        g_col[atomicAdd(&g_cursor[d.z], 1)] = s.z;
        g_col[atomicAdd(&g_cursor[d.w], 1)] = s.w;
    } else {
        for (int j = 0; j < 4; j++)
            if (base + j < e_cnt) {
                int dd = dst[base + j];
                int p = atomicAdd(&g_cursor[dd], 1);
                g_col[p] = src[base + j];
            }
    }
}

// ---------------- staging helpers ----------------
__device__ __forceinline__ void stage_A(__half* as, const float* A, int m0, int M, int tid) {
    #pragma unroll
    for (int i = 0; i < 8; i++) {
        int idx = tid + i * 256;
        int row = idx >> 5;
        int c4  = (idx & 31) * 4;
        int gm = m0 + row;
        float4 v = (gm < M) ? __ldg((const float4*)(A + (size_t)gm * D + c4))
                            : make_float4(0.f, 0.f, 0.f, 0.f);
        uint2 u = make_uint2(f2h2(v.x, v.y), f2h2(v.z, v.w));
        *(uint2*)(&as[row * KPAD + c4]) = u;
    }
}
__device__ __forceinline__ void stage_Ah(__half* as, const __half* A, int m0, int M, int tid) {
    #pragma unroll
    for (int i = 0; i < 4; i++) {
        int idx = tid + i * 256;
        int row = idx >> 4;
        int c8  = (idx & 15) * 8;
        int gm = m0 + row;
        uint4 u = (gm < M) ? __ldg((const uint4*)(A + (size_t)gm * D + c8))
                           : make_uint4(0u, 0u, 0u, 0u);
        *(uint4*)(&as[row * KPAD + c8]) = u;
    }
}
__device__ __forceinline__ void stage_Wh(__half* ws, const __half* W, int tid) {
    #pragma unroll
    for (int i = 0; i < 8; i++) {
        int idx = tid + i * 256;
        int row = idx >> 4;
        int c8  = (idx & 15) * 8;
        uint4 u = __ldg((const uint4*)(W + (size_t)row * D + c8));
        *(uint4*)(&ws[row * KPAD + c8]) = u;
    }
}

// ---------------- mm_dual: out0(h0,fp16) = gelu(A@W0^T+b0), out1(shortcut,fp16) = A@W1^T+b1 ----------------
__global__ __launch_bounds__(256, 2)
void mm_dual_kernel(const float* __restrict__ A,
                    const __half* __restrict__ W0, const float* __restrict__ b0v,
                    const __half* __restrict__ W1, const float* __restrict__ b1v,
                    __half* __restrict__ out0, __half* __restrict__ out1, int M) {
    extern __shared__ __half smemh[];
    __half* as = smemh;
    __half* ws = smemh + 64 * KPAD;
    int tid = threadIdx.x, lane = tid & 31, wid = tid >> 5;
    int wm = wid & 1, wn = wid >> 1;
    int m0 = blockIdx.x * 64;
    int qr = lane >> 2, qc = lane & 3;

    unsigned aaddr0 = ldsm_a_addr(as, wm * 32, lane);
    unsigned aaddr1 = aaddr0 + 16 * KPAD * 2;
    unsigned baddr0 = ldsm_b_addr(ws, wn * 32, lane);
    unsigned baddr1 = baddr0 + 16 * KPAD * 2;

    float acc[2][2][4][4];
    #pragma unroll
    for (int w = 0; w < 2; w++)
        #pragma unroll
        for (int i = 0; i < 2; i++)
            #pragma unroll
            for (int j = 0; j < 4; j++)
                #pragma unroll
                for (int k = 0; k < 4; k++) acc[w][i][j][k] = 0.f;

    stage_A(as, A, m0, M, tid);
    #pragma unroll
    for (int w = 0; w < 2; w++) {
        if (w) __syncthreads();
        stage_Wh(ws, w ? W1 : W0, tid);
        __syncthreads();
        #pragma unroll
        for (int ks = 0; ks < 8; ks++) {
            unsigned koff = ks * 32;
            unsigned afr[2][4], bfr[8];
            ldsm_x4(afr[0], aaddr0 + koff);
            ldsm_x4(afr[1], aaddr1 + koff);
            ldsm_x4(&bfr[0], baddr0 + koff);
            ldsm_x4(&bfr[4], baddr1 + koff);
            #pragma unroll
            for (int m = 0; m < 2; m++)
                #pragma unroll
                for (int n = 0; n < 4; n++)
                    mma_f16(acc[w][m][n], afr[m], &bfr[2 * n]);
        }
    }

    int cpair = qc * 2;
    #pragma unroll
    for (int n = 0; n < 4; n++) {
        int col = wn * 32 + n * 8 + cpair;
        float b00 = __ldg(b0v + col), b01 = __ldg(b0v + col + 1);
        float b10 = __ldg(b1v + col), b11 = __ldg(b1v + col + 1);
        #pragma unroll
        for (int m = 0; m < 2; m++) {
            int gr = m0 + wm * 32 + m * 16 + qr;
            if (gr < M) {
                *(unsigned*)(out0 + (size_t)gr * D + col) =
                    f2h2(gelu_f(acc[0][m][n][0] + b00), gelu_f(acc[0][m][n][1] + b01));
                *(unsigned*)(out1 + (size_t)gr * D + col) =
                    f2h2(acc[1][m][n][0] + b10, acc[1][m][n][1] + b11);
            }
            if (gr + 8 < M) {
                *(unsigned*)(out0 + (size_t)(gr + 8) * D + col) =
                    f2h2(gelu_f(acc[0][m][n][2] + b00), gelu_f(acc[0][m][n][3] + b01));
                *(unsigned*)(out1 + (size_t)(gr + 8) * D + col) =
                    f2h2(acc[1][m][n][2] + b10, acc[1][m][n][3] + b11);
            }
        }
    }
}

// ---------------- device bodies for the fused post-join kernel ----------------
// agg phase: warp per node, grid-stride. Accumulation order identical to R14
// (sequential i, i+1, i+2, i+3) -> bit-identical results.
__device__ void agg_phase(const __half* __restrict__ h, __half* __restrict__ meanout,
                          int Mn, int gw, int lane, int nw) {
    for (int w = gw; w < Mn; w += nw) {
        int s = g_rp[w], e = g_rp[w + 1];
        float a0 = 0.f, a1 = 0.f, a2 = 0.f, a3 = 0.f;
        int i = s;
        for (; i + 4 <= e; i += 4) {
            int c0 = __ldg(&g_col[i]);
            int c1 = __ldg(&g_col[i + 1]);
            int c2 = __ldg(&g_col[i + 2]);
            int c3 = __ldg(&g_col[i + 3]);
            uint2 u0 = __ldg((const uint2*)(h + (size_t)c0 * D) + lane);
            uint2 u1 = __ldg((const uint2*)(h + (size_t)c1 * D) + lane);
            uint2 u2 = __ldg((const uint2*)(h + (size_t)c2 * D) + lane);
            uint2 u3 = __ldg((const uint2*)(h + (size_t)c3 * D) + lane);
            float2 f0, f1;
            f0 = __half22float2(*(__half2*)&u0.x); f1 = __half22float2(*(__half2*)&u0.y);
            a0 += f0.x; a1 += f0.y; a2 += f1.x; a3 += f1.y;
            f0 = __half22float2(*(__half2*)&u1.x); f1 = __half22float2(*(__half2*)&u1.y);
            a0 += f0.x; a1 += f0.y; a2 += f1.x; a3 += f1.y;
            f0 = __half22float2(*(__half2*)&u2.x); f1 = __half22float2(*(__half2*)&u2.y);
            a0 += f0.x; a1 += f0.y; a2 += f1.x; a3 += f1.y;
            f0 = __half22float2(*(__half2*)&u3.x); f1 = __half22float2(*(__half2*)&u3.y);
            a0 += f0.x; a1 += f0.y; a2 += f1.x; a3 += f1.y;
        }
        for (; i < e; i++) {
            int c0 = __ldg(&g_col[i]);
            uint2 u0 = __ldg((const uint2*)(h + (size_t)c0 * D) + lane);
            float2 f0 = __half22float2(*(__half2*)&u0.x);
            float2 f1 = __half22float2(*(__half2*)&u0.y);
            a0 += f0.x; a1 += f0.y; a2 += f1.x; a3 += f1.y;
        }
        float inv = 1.0f / (float)max(e - s, 1);
        uint2 o;
        o.x = f2h2(a0 * inv, a1 * inv);
        o.y = f2h2(a2 * inv, a3 * inv);
        *((uint2*)(meanout + (size_t)w * D) + lane) = o;
    }
}

// one sage tile: out = gelu( LN( A0@W0^T + A1@W1^T + bias ) [+ sc] )
__device__ void sage_tile(__half* smemh,
                          const __half* __restrict__ A0, const __half* __restrict__ W0,
                          const __half* __restrict__ A1, const __half* __restrict__ W1,
                          const float* __restrict__ bias,
                          const float* __restrict__ gamma, const float* __restrict__ beta,
                          const __half* __restrict__ sc,
                          void* __restrict__ outp, bool out_half,
                          int M, int m0, int tid, int lane, int wid) {
    __half* as = smemh;
    __half* ws = smemh + 64 * KPAD;
    int wm = wid & 1, wn = wid >> 1;
    int qr = lane >> 2, qc = lane & 3;

    unsigned aaddr0 = ldsm_a_addr(as, wm * 32, lane);
    unsigned aaddr1 = aaddr0 + 16 * KPAD * 2;
    unsigned baddr0 = ldsm_b_addr(ws, wn * 32, lane);
    unsigned baddr1 = baddr0 + 16 * KPAD * 2;

    float acc[2][4][4];
    #pragma unroll
    for (int i = 0; i < 2; i++)
        #pragma unroll
        for (int j = 0; j < 4; j++)
            #pragma unroll
            for (int k = 0; k < 4; k++) acc[i][j][k] = 0.f;

    #pragma unroll
    for (int ph = 0; ph < 2; ph++) {
        if (ph) __syncthreads();
        stage_Ah(as, ph ? A1 : A0, m0, M, tid);
        stage_Wh(ws, ph ? W1 : W0, tid);
        __syncthreads();
        #pragma unroll
        for (int ks = 0; ks < 8; ks++) {
            unsigned koff = ks * 32;
            unsigned afr[2][4], bfr[8];
            ldsm_x4(afr[0], aaddr0 + koff);
            ldsm_x4(afr[1], aaddr1 + koff);
            ldsm_x4(&bfr[0], baddr0 + koff);
            ldsm_x4(&bfr[4], baddr1 + koff);
            #pragma unroll
            for (int m = 0; m < 2; m++)
                #pragma unroll
                for (int n = 0; n < 4; n++)
                    mma_f16(acc[m][n], afr[m], &bfr[2 * n]);
        }
    }

    // spill tile (+bias) to smem as fp32, then warp-per-row LN epilogue
    float* os = (float*)smemh;   // reuse, [64][MMPAD] fp32
    __syncthreads();
    int cpair = qc * 2;
    #pragma unroll
    for (int n = 0; n < 4; n++) {
        int col = wn * 32 + n * 8 + cpair;
        float b0 = __ldg(bias + col), b1 = __ldg(bias + col + 1);
        #pragma unroll
        for (int m = 0; m < 2; m++) {
            int r = wm * 32 + m * 16 + qr;
            os[r * MMPAD + col]           = acc[m][n][0] + b0;
            os[r * MMPAD + col + 1]       = acc[m][n][1] + b1;
            os[(r + 8) * MMPAD + col]     = acc[m][n][2] + b0;
            os[(r + 8) * MMPAD + col + 1] = acc[m][n][3] + b1;
        }
    }
    __syncthreads();

    float4 g = __ldg((const float4*)gamma + lane);
    float4 bb = __ldg((const float4*)beta + lane);
    for (int rr = wid; rr < 64; rr += 8) {
        int gr = m0 + rr;
        if (gr >= M) break;
        float4 v = *(const float4*)&os[rr * MMPAD + lane * 4];
        float s = v.x + v.y + v.z + v.w;
        #pragma unroll
        for (int off = 16; off; off >>= 1) s += __shfl_xor_sync(0xFFFFFFFFu, s, off);
        float mu = s * (1.0f / 128.0f);
        float dx = v.x - mu, dy = v.y - mu, dz = v.z - mu, dw = v.w - mu;
        float q = dx * dx + dy * dy + dz * dz + dw * dw;
        #pragma unroll
        for (int off = 16; off; off >>= 1) q += __shfl_xor_sync(0xFFFFFFFFu, q, off);
        float r = rsqrtf(q * (1.0f / 128.0f) + 1e-5f);
        float4 o;
        o.x = dx * r * g.x + bb.x;
        o.y = dy * r * g.y + bb.y;
        o.z = dz * r * g.z + bb.z;
        o.w = dw * r * g.w + bb.w;
        if (sc != nullptr) {
            uint2 su = __ldg((const uint2*)(sc + (size_t)gr * D) + lane);
            float2 s0 = __half22float2(*(__half2*)&su.x);
            float2 s1 = __half22float2(*(__half2*)&su.y);
            o.x += s0.x; o.y += s0.y; o.z += s1.x; o.w += s1.y;
        }
        o.x = gelu_f(o.x); o.y = gelu_f(o.y); o.z = gelu_f(o.z); o.w = gelu_f(o.w);
        if (out_half) {
            __half* oh = (__half*)outp;
            uint2 u;
            u.x = f2h2(o.x, o.y);
            u.y = f2h2(o.z, o.w);
            *((uint2*)(oh + (size_t)gr * D) + lane) = u;
        } else {
            float* of = (float*)outp;
            *(float4*)(of + (size_t)gr * D + lane * 4) = o;
        }
    }
}

// ---------------- fused post-join persistent kernel ----------------
// agg1 -> sage1 -> agg2 -> sage2 with grid barriers between phases.
// All blocks resident: launch_bounds(256,3), grid = SMcount*3.
__global__ __launch_bounds__(256, 3)
void fused_post_kernel(const __half* __restrict__ h0,
                       const __half* __restrict__ g1lw, const __half* __restrict__ g1rw,
                       const float* __restrict__ g1lb,
                       const float* __restrict__ n1g, const float* __restrict__ n1b,
                       const __half* __restrict__ g2lw, const __half* __restrict__ g2rw,
                       const float* __restrict__ g2lb,
                       const float* __restrict__ n2g, const float* __restrict__ n2b,
                       const __half* __restrict__ shrt,
                       __half* __restrict__ meanb, __half* __restrict__ tb,
                       float* __restrict__ out, int M) {
    extern __shared__ __half smemh[];
    int tid = threadIdx.x, lane = tid & 31, wid = tid >> 5;
    int nblocks = gridDim.x;
    int nwarps = nblocks * 8;
    int gw = blockIdx.x * 8 + wid;
    int ntiles = (M + 63) / 64;

    // phase A: agg1  h0 -> meanb
    agg_phase(h0, meanb, M, gw, lane, nwarps);
    grid_barrier(nblocks);

    // phase B: sage1 -> tb (fp16)
    for (int t = blockIdx.x; t < ntiles; t += nblocks) {
        __syncthreads();
        sage_tile(smemh, meanb, g1lw, h0, g1rw, g1lb, n1g, n1b, nullptr,
                  tb, true, M, t * 64, tid, lane, wid);
    }
    grid_barrier(nblocks);

    // phase C: agg2  tb -> meanb
    agg_phase(tb, meanb, M, gw, lane, nwarps);
    grid_barrier(nblocks);

    // phase D: sage2 -> out (fp32)
    for (int t = blockIdx.x; t < ntiles; t += nblocks) {
        __syncthreads();
        sage_tile(smemh, meanb, g2lw, tb, g2rw, g2lb, n2g, n2b, shrt,
                  out, false, M, t * 64, tid, lane, wid);
    }
}

extern "C" void kernel_launch(void* const* d_in, const int* in_sizes, int n_in,
                              void* d_out, int out_size) {
    const float* x     = (const float*)d_in[0];
    const int*   edges = (const int*)  d_in[1];
    const float* dp_w  = (const float*)d_in[2];
    const float* dp_b  = (const float*)d_in[3];
    const float* sc_w  = (const float*)d_in[4];
    const float* sc_b  = (const float*)d_in[5];
    const float* g1_lw = (const float*)d_in[6];
    const float* g1_lb = (const float*)d_in[7];
    const float* g1_rw = (const float*)d_in[8];
    const float* n1_g  = (const float*)d_in[9];
    const float* n1_b  = (const float*)d_in[10];
    const float* g2_lw = (const float*)d_in[11];
    const float* g2_lb = (const float*)d_in[12];
    const float* g2_rw = (const float*)d_in[13];
    const float* n2_g  = (const float*)d_in[14];
    const float* n2_b  = (const float*)d_in[15];
    float* out = (float*)d_out;

    int M = in_sizes[0] / D;      // 50000
    int E = in_sizes[1] / 2;      // 640000
    const int* srcp = edges;
    const int* dstp = edges + E;

    __half *h0, *shrt, *meanb, *tb, *w16, *w16b;
    int *degp;
    unsigned long long *descp;
    cudaGetSymbolAddress((void**)&h0,    g_h0);
    cudaGetSymbolAddress((void**)&shrt,  g_short);
    cudaGetSymbolAddress((void**)&meanb, g_mean);
    cudaGetSymbolAddress((void**)&tb,    g_t);
    cudaGetSymbolAddress((void**)&w16,   g_w16);
    cudaGetSymbolAddress((void**)&w16b,  g_w16b);
    cudaGetSymbolAddress((void**)&degp,  g_deg);
    cudaGetSymbolAddress((void**)&descp, g_desc);
    __half* dpw_h  = w16 + 0 * D * D;
    __half* scw_h  = w16 + 1 * D * D;
    __half* g1lw_h = w16 + 2 * D * D;
    __half* g1rw_h = w16 + 3 * D * D;
    __half* g2lw_h = w16b + 0 * D * D;
    __half* g2rw_h = w16b + 1 * D * D;

    const int MM_SMEM = (64 + 128) * KPAD * (int)sizeof(__half);  // 52224 B
    cudaFuncSetAttribute(mm_dual_kernel, cudaFuncAttributeMaxDynamicSharedMemorySize, MM_SMEM);
    cudaFuncSetAttribute(fused_post_kernel, cudaFuncAttributeMaxDynamicSharedMemorySize, MM_SMEM);

    int nsm = 148;
    cudaDeviceGetAttribute(&nsm, cudaDevAttrMultiProcessorCount, 0);
    int pblocks = nsm * 3;

    int nblk = (M + 63) / 64;
    int nb256 = (M + 255) / 256;
    int egrid4 = (E + 1023) / 1024;

    cudaStream_t side = g_fork.side;

    // ---- fork: CSR build on side stream, concurrent with wconv + mm_dual ----
    cudaEventRecord(g_fork.evFork, 0);
    cudaStreamWaitEvent(side, g_fork.evFork, 0);

    cudaMemsetAsync(degp, 0, NN * sizeof(int), side);
    cudaMemsetAsync(descp, 0, 256 * sizeof(unsigned long long), side);
    hist_kernel<<<egrid4, 256, 0, side>>>(dstp, E);
    scan_lookback_kernel<<<nb256, 256, 0, side>>>(M);
    fill_kernel<<<egrid4, 256, 0, side>>>(srcp, dstp, E);
    cudaEventRecord(g_fork.evJoin, side);

    // ---- main branch: weights -> fp16, then h0/shortcut GEMM ----
    wconv_kernel<<<192, 256>>>(dp_w, sc_w, g1_lw, g1_rw, g2_lw, g2_rw);
    mm_dual_kernel<<<nblk, 256, MM_SMEM>>>(x, dpw_h, dp_b, scw_h, sc_b, h0, shrt, M);

    // ---- join: fused post section needs both CSR and h0 ----
    cudaStreamWaitEvent(0, g_fork.evJoin, 0);

    fused_post_kernel<<<pblocks, 256, MM_SMEM>>>(
        h0, g1lw_h, g1rw_h, g1_lb, n1_g, n1_b,
        g2lw_h, g2rw_h, g2_lb, n2_g, n2_b,
        shrt, meanb, tb, out, M);
}

// round 16
// speedup vs baseline: 1.1671x; 1.1671x over previous
#include <cuda_runtime.h>
#include <cuda_fp16.h>
#include <math.h>

#define D 128
#define NN 50000
#define NE 640000
#define MMPAD 132
#define KPAD 136   // halves per row in fp16 staging (128 + 8 pad)

// ---- scratch (device globals: allocation-free) ----
__device__ __half g_h0[NN * D];     // h0 (fp16)
__device__ __half g_short[NN * D];  // shortcut (fp16)
__device__ __half g_mean[NN * D];   // mean aggregation buffer (fp16)
__device__ __half g_t[NN * D];      // h1 (fp16)
__device__ __half g_w16[4][D * D];  // fp16 weights: dp_w, sc_w, g1_lw, g1_rw
__device__ __half g_w16b[2][D * D]; // fp16 weights: g2_lw, g2_rw
__device__ int    g_deg[NN];
__device__ int    g_cursor[NN];
__device__ int    g_rp[NN + 1];
__device__ int    g_col[NE];
__device__ unsigned long long g_desc[256];   // lookback descriptors

// ---- host-side stream/event for forked graph capture (host objects, not device mem) ----
struct ForkCtx {
    cudaStream_t side;
    cudaEvent_t evFork, evJoin;
    ForkCtx() {
        cudaStreamCreateWithFlags(&side, cudaStreamNonBlocking);
        cudaEventCreateWithFlags(&evFork, cudaEventDisableTiming);
        cudaEventCreateWithFlags(&evJoin, cudaEventDisableTiming);
    }
};
static ForkCtx g_fork;

__device__ __forceinline__ float gelu_f(float x) {
    return 0.5f * x * (1.0f + erff(x * 0.70710678118654752f));
}

__device__ __forceinline__ unsigned f2h2(float a, float b) {
    __half2 h = __floats2half2_rn(a, b);
    return *(unsigned*)&h;
}

__device__ __forceinline__ void mma_f16(float* c, const unsigned* a, const unsigned* b) {
    asm volatile(
        "mma.sync.aligned.m16n8k16.row.col.f32.f16.f16.f32 "
        "{%0,%1,%2,%3},{%4,%5,%6,%7},{%8,%9},{%0,%1,%2,%3};"
        : "+f"(c[0]), "+f"(c[1]), "+f"(c[2]), "+f"(c[3])
        : "r"(a[0]), "r"(a[1]), "r"(a[2]), "r"(a[3]), "r"(b[0]), "r"(b[1]));
}

__device__ __forceinline__ void ldsm_x4(unsigned* r, unsigned addr) {
    asm volatile("ldmatrix.sync.aligned.m8n8.x4.shared.b16 {%0,%1,%2,%3}, [%4];"
        : "=r"(r[0]), "=r"(r[1]), "=r"(r[2]), "=r"(r[3]) : "r"(addr));
}

__device__ __forceinline__ unsigned ldsm_a_addr(const __half* as, int ar, int lane) {
    return (unsigned)__cvta_generic_to_shared(
        &as[(ar + (lane & 15)) * KPAD + ((lane >> 4) * 8)]);
}
__device__ __forceinline__ unsigned ldsm_b_addr(const __half* ws, int nb, int lane) {
    return (unsigned)__cvta_generic_to_shared(
        &ws[(nb + ((lane >> 4) * 8) + (lane & 7)) * KPAD + (((lane >> 3) & 1) * 8)]);
}

// ---------------- one-time weight fp32 -> fp16 conversion ----------------
__global__ void wconv_kernel(const float* __restrict__ w0, const float* __restrict__ w1,
                             const float* __restrict__ w2, const float* __restrict__ w3,
                             const float* __restrict__ w4, const float* __restrict__ w5) {
    int mat = blockIdx.x >> 5;
    int off = (((blockIdx.x & 31) * 256) + threadIdx.x) * 2;
    const float* src;
    __half* dst;
    switch (mat) {
        case 0:  src = w0; dst = g_w16[0];  break;
        case 1:  src = w1; dst = g_w16[1];  break;
        case 2:  src = w2; dst = g_w16[2];  break;
        case 3:  src = w3; dst = g_w16[3];  break;
        case 4:  src = w4; dst = g_w16b[0]; break;
        default: src = w5; dst = g_w16b[1]; break;
    }
    float2 v = *(const float2*)(src + off);
    *(unsigned*)(dst + off) = f2h2(v.x, v.y);
}

// ---------------- CSR build ----------------
// zero g_deg + g_desc in one launch
__global__ void zero2_kernel(int n) {
    int i = blockIdx.x * blockDim.x + threadIdx.x;
    if (i < n) g_deg[i] = 0;
    if (i < 256) g_desc[i] = 0ULL;
}

__global__ void hist_kernel(const int* __restrict__ dst, int e_cnt) {
    int base = (blockIdx.x * blockDim.x + threadIdx.x) * 4;
    if (base + 4 <= e_cnt) {
        int4 d = *(const int4*)(dst + base);
        atomicAdd(&g_deg[d.x], 1);
        atomicAdd(&g_deg[d.y], 1);
        atomicAdd(&g_deg[d.z], 1);
        atomicAdd(&g_deg[d.w], 1);
    } else {
        for (int j = 0; j < 4; j++)
            if (base + j < e_cnt) atomicAdd(&g_deg[dst[base + j]], 1);
    }
}

__global__ void scan_lookback_kernel(int n) {
    __shared__ int wsum[8];
    __shared__ int s_total;
    __shared__ int s_excl;
    int tid = threadIdx.x, lane = tid & 31, wid = tid >> 5;
    int bid = blockIdx.x;
    int i = bid * 256 + tid;
    int v = (i < n) ? g_deg[i] : 0;
    int x = v;
    #pragma unroll
    for (int off = 1; off < 32; off <<= 1) {
        int t = __shfl_up_sync(0xFFFFFFFFu, x, off);
        if (lane >= off) x += t;
    }
    if (lane == 31) wsum[wid] = x;
    __syncthreads();
    if (tid < 32) {
        int w = (tid < 8) ? wsum[tid] : 0;
        #pragma unroll
        for (int off = 1; off < 8; off <<= 1) {
            int t = __shfl_up_sync(0xFFFFFFFFu, w, off);
            if (tid >= off) w += t;
        }
        if (tid < 8) wsum[tid] = w;
    }
    __syncthreads();
    int incl = x + ((wid > 0) ? wsum[wid - 1] : 0);
    if (tid == 255) { s_total = incl; }
    __syncthreads();
    int total = s_total;

    if (tid == 0) {
        __threadfence();
        unsigned long long st = (bid == 0) ? (2ULL << 32) : (1ULL << 32);
        atomicExch(&g_desc[bid], st | (unsigned)total);
        if (bid == 0) s_excl = 0;
    }
    if (bid > 0 && wid == 0) {
        int j = bid - 1 - lane;
        long ex = 0;
        while (true) {
            unsigned long long d;
            unsigned st;
            if (j >= 0) {
                do { d = atomicAdd(&g_desc[j], 0ULL); st = (unsigned)(d >> 32); } while (st == 0);
            } else {
                d = (2ULL << 32); st = 2u;
            }
            unsigned mask = __ballot_sync(0xFFFFFFFFu, st == 2u);
            if (mask) {
                int firstP = __ffs(mask) - 1;
                unsigned contrib = (lane <= firstP) ? (unsigned)d : 0u;
                #pragma unroll
                for (int off = 16; off; off >>= 1)
                    contrib += __shfl_xor_sync(0xFFFFFFFFu, contrib, off);
                ex += (long)contrib;
                break;
            } else {
                unsigned contrib = (unsigned)d;
                #pragma unroll
                for (int off = 16; off; off >>= 1)
                    contrib += __shfl_xor_sync(0xFFFFFFFFu, contrib, off);
                ex += (long)contrib;
                j -= 32;
            }
        }
        if (lane == 0) {
            __threadfence();
            atomicExch(&g_desc[bid], (2ULL << 32) | (unsigned)(ex + total));
            s_excl = (int)ex;
        }
    }
    __syncthreads();
    int off = s_excl;
    if (i < n) {
        int gincl = incl + off;
        g_rp[i + 1] = gincl;
        g_cursor[i] = gincl - v;
    }
    if (i == 0) g_rp[0] = 0;
}

__global__ void fill_kernel(const int* __restrict__ src, const int* __restrict__ dst, int e_cnt) {
    int base = (blockIdx.x * blockDim.x + threadIdx.x) * 4;
    if (base + 4 <= e_cnt) {
        int4 s = *(const int4*)(src + base);
        int4 d = *(const int4*)(dst + base);
        g_col[atomicAdd(&g_cursor[d.x], 1)] = s.x;
        g_col[atomicAdd(&g_cursor[d.y], 1)] = s.y;
        g_col[atomicAdd(&g_cursor[d.z], 1)] = s.z;
        g_col[atomicAdd(&g_cursor[d.w], 1)] = s.w;
    } else {
        for (int j = 0; j < 4; j++)
            if (base + j < e_cnt) {
                int dd = dst[base + j];
                int p = atomicAdd(&g_cursor[dd], 1);
                g_col[p] = src[base + j];
            }
    }
}

// ---------------- mean aggregation: warp per destination node (fp16 rows) ----------------
// Unroll-by-4 software pipeline; accumulation order strictly sequential
// (i, i+1, i+2, i+3) -> bit-identical to the serial loop.
__global__ void agg_kernel(const __half* __restrict__ h, __half* __restrict__ meanout, int n) {
    int w = (int)((blockIdx.x * blockDim.x + threadIdx.x) >> 5);
    int lane = threadIdx.x & 31;
    if (w >= n) return;
    int s = g_rp[w], e = g_rp[w + 1];
    float a0 = 0.f, a1 = 0.f, a2 = 0.f, a3 = 0.f;
    int i = s;
    for (; i + 4 <= e; i += 4) {
        int c0 = __ldg(&g_col[i]);
        int c1 = __ldg(&g_col[i + 1]);
        int c2 = __ldg(&g_col[i + 2]);
        int c3 = __ldg(&g_col[i + 3]);
        uint2 u0 = __ldg((const uint2*)(h + (size_t)c0 * D) + lane);
        uint2 u1 = __ldg((const uint2*)(h + (size_t)c1 * D) + lane);
        uint2 u2 = __ldg((const uint2*)(h + (size_t)c2 * D) + lane);
        uint2 u3 = __ldg((const uint2*)(h + (size_t)c3 * D) + lane);
        float2 f0, f1;
        f0 = __half22float2(*(__half2*)&u0.x); f1 = __half22float2(*(__half2*)&u0.y);
        a0 += f0.x; a1 += f0.y; a2 += f1.x; a3 += f1.y;
        f0 = __half22float2(*(__half2*)&u1.x); f1 = __half22float2(*(__half2*)&u1.y);
        a0 += f0.x; a1 += f0.y; a2 += f1.x; a3 += f1.y;
        f0 = __half22float2(*(__half2*)&u2.x); f1 = __half22float2(*(__half2*)&u2.y);
        a0 += f0.x; a1 += f0.y; a2 += f1.x; a3 += f1.y;
        f0 = __half22float2(*(__half2*)&u3.x); f1 = __half22float2(*(__half2*)&u3.y);
        a0 += f0.x; a1 += f0.y; a2 += f1.x; a3 += f1.y;
    }
    for (; i < e; i++) {
        int c0 = __ldg(&g_col[i]);
        uint2 u0 = __ldg((const uint2*)(h + (size_t)c0 * D) + lane);
        float2 f0 = __half22float2(*(__half2*)&u0.x);
        float2 f1 = __half22float2(*(__half2*)&u0.y);
        a0 += f0.x; a1 += f0.y; a2 += f1.x; a3 += f1.y;
    }
    float inv = 1.0f / (float)max(e - s, 1);
    uint2 o;
    o.x = f2h2(a0 * inv, a1 * inv);
    o.y = f2h2(a2 * inv, a3 * inv);
    *((uint2*)(meanout + (size_t)w * D) + lane) = o;
}

// ---------------- staging helpers ----------------
__device__ __forceinline__ void stage_A(__half* as, const float* A, int m0, int M, int tid) {
    #pragma unroll
    for (int i = 0; i < 8; i++) {
        int idx = tid + i * 256;
        int row = idx >> 5;
        int c4  = (idx & 31) * 4;
        int gm = m0 + row;
        float4 v = (gm < M) ? __ldg((const float4*)(A + (size_t)gm * D + c4))
                            : make_float4(0.f, 0.f, 0.f, 0.f);
        uint2 u = make_uint2(f2h2(v.x, v.y), f2h2(v.z, v.w));
        *(uint2*)(&as[row * KPAD + c4]) = u;
    }
}
__device__ __forceinline__ void stage_Ah(__half* as, const __half* A, int m0, int M, int tid) {
    #pragma unroll
    for (int i = 0; i < 4; i++) {
        int idx = tid + i * 256;
        int row = idx >> 4;
        int c8  = (idx & 15) * 8;
        int gm = m0 + row;
        uint4 u = (gm < M) ? __ldg((const uint4*)(A + (size_t)gm * D + c8))
                           : make_uint4(0u, 0u, 0u, 0u);
        *(uint4*)(&as[row * KPAD + c8]) = u;
    }
}
__device__ __forceinline__ void stage_Wh(__half* ws, const __half* W, int tid) {
    #pragma unroll
    for (int i = 0; i < 8; i++) {
        int idx = tid + i * 256;
        int row = idx >> 4;
        int c8  = (idx & 15) * 8;
        uint4 u = __ldg((const uint4*)(W + (size_t)row * D + c8));
        *(uint4*)(&ws[row * KPAD + c8]) = u;
    }
}

// ---------------- mm_dual: out0(h0,fp16) = gelu(A@W0^T+b0), out1(shortcut,fp16) = A@W1^T+b1 ----------------
__global__ __launch_bounds__(256, 2)
void mm_dual_kernel(const float* __restrict__ A,
                    const __half* __restrict__ W0, const float* __restrict__ b0v,
                    const __half* __restrict__ W1, const float* __restrict__ b1v,
                    __half* __restrict__ out0, __half* __restrict__ out1, int M) {
    extern __shared__ __half smemh[];
    __half* as = smemh;
    __half* ws = smemh + 64 * KPAD;
    int tid = threadIdx.x, lane = tid & 31, wid = tid >> 5;
    int wm = wid & 1, wn = wid >> 1;
    int m0 = blockIdx.x * 64;
    int qr = lane >> 2, qc = lane & 3;

    unsigned aaddr0 = ldsm_a_addr(as, wm * 32, lane);
    unsigned aaddr1 = aaddr0 + 16 * KPAD * 2;
    unsigned baddr0 = ldsm_b_addr(ws, wn * 32, lane);
    unsigned baddr1 = baddr0 + 16 * KPAD * 2;

    float acc[2][2][4][4];
    #pragma unroll
    for (int w = 0; w < 2; w++)
        #pragma unroll
        for (int i = 0; i < 2; i++)
            #pragma unroll
            for (int j = 0; j < 4; j++)
                #pragma unroll
                for (int k = 0; k < 4; k++) acc[w][i][j][k] = 0.f;

    stage_A(as, A, m0, M, tid);
    #pragma unroll
    for (int w = 0; w < 2; w++) {
        if (w) __syncthreads();
        stage_Wh(ws, w ? W1 : W0, tid);
        __syncthreads();
        #pragma unroll
        for (int ks = 0; ks < 8; ks++) {
            unsigned koff = ks * 32;
            unsigned afr[2][4], bfr[8];
            ldsm_x4(afr[0], aaddr0 + koff);
            ldsm_x4(afr[1], aaddr1 + koff);
            ldsm_x4(&bfr[0], baddr0 + koff);
            ldsm_x4(&bfr[4], baddr1 + koff);
            #pragma unroll
            for (int m = 0; m < 2; m++)
                #pragma unroll
                for (int n = 0; n < 4; n++)
                    mma_f16(acc[w][m][n], afr[m], &bfr[2 * n]);
        }
    }

    int cpair = qc * 2;
    #pragma unroll
    for (int n = 0; n < 4; n++) {
        int col = wn * 32 + n * 8 + cpair;
        float b00 = __ldg(b0v + col), b01 = __ldg(b0v + col + 1);
        float b10 = __ldg(b1v + col), b11 = __ldg(b1v + col + 1);
        #pragma unroll
        for (int m = 0; m < 2; m++) {
            int gr = m0 + wm * 32 + m * 16 + qr;
            if (gr < M) {
                *(unsigned*)(out0 + (size_t)gr * D + col) =
                    f2h2(gelu_f(acc[0][m][n][0] + b00), gelu_f(acc[0][m][n][1] + b01));
                *(unsigned*)(out1 + (size_t)gr * D + col) =
                    f2h2(acc[1][m][n][0] + b10, acc[1][m][n][1] + b11);
            }
            if (gr + 8 < M) {
                *(unsigned*)(out0 + (size_t)(gr + 8) * D + col) =
                    f2h2(gelu_f(acc[0][m][n][2] + b00), gelu_f(acc[0][m][n][3] + b01));
                *(unsigned*)(out1 + (size_t)(gr + 8) * D + col) =
                    f2h2(acc[1][m][n][2] + b10, acc[1][m][n][3] + b11);
            }
        }
    }
}

// ---------------- mm_sage: out = gelu( LN( A0@W0^T + A1@W1^T + bias ) [+ sc] ) ----------------
template <bool OUT_HALF>
__global__ __launch_bounds__(256, 3)
void mm_sage_kernel(const __half* __restrict__ A0, const __half* __restrict__ W0,
                    const __half* __restrict__ A1, const __half* __restrict__ W1,
                    const float* __restrict__ bias,
                    const float* __restrict__ gamma, const float* __restrict__ beta,
                    const __half* __restrict__ sc,
                    void* __restrict__ outp, int M) {
    extern __shared__ __half smemh[];
    __half* as = smemh;
    __half* ws = smemh + 64 * KPAD;
    int tid = threadIdx.x, lane = tid & 31, wid = tid >> 5;
    int wm = wid & 1, wn = wid >> 1;
    int m0 = blockIdx.x * 64;
    int qr = lane >> 2, qc = lane & 3;

    unsigned aaddr0 = ldsm_a_addr(as, wm * 32, lane);
    unsigned aaddr1 = aaddr0 + 16 * KPAD * 2;
    unsigned baddr0 = ldsm_b_addr(ws, wn * 32, lane);
    unsigned baddr1 = baddr0 + 16 * KPAD * 2;

    float acc[2][4][4];
    #pragma unroll
    for (int i = 0; i < 2; i++)
        #pragma unroll
        for (int j = 0; j < 4; j++)
            #pragma unroll
            for (int k = 0; k < 4; k++) acc[i][j][k] = 0.f;

    #pragma unroll
    for (int ph = 0; ph < 2; ph++) {
        if (ph) __syncthreads();
        stage_Ah(as, ph ? A1 : A0, m0, M, tid);
        stage_Wh(ws, ph ? W1 : W0, tid);
        __syncthreads();
        #pragma unroll
        for (int ks = 0; ks < 8; ks++) {
            unsigned koff = ks * 32;
            unsigned afr[2][4], bfr[8];
            ldsm_x4(afr[0], aaddr0 + koff);
            ldsm_x4(afr[1], aaddr1 + koff);
            ldsm_x4(&bfr[0], baddr0 + koff);
            ldsm_x4(&bfr[4], baddr1 + koff);
            #pragma unroll
            for (int m = 0; m < 2; m++)
                #pragma unroll
                for (int n = 0; n < 4; n++)
                    mma_f16(acc[m][n], afr[m], &bfr[2 * n]);
        }
    }

    // spill tile (+bias) to smem as fp32, then warp-per-row LN epilogue
    float* os = (float*)smemh;   // reuse, [64][MMPAD] fp32
    __syncthreads();
    int cpair = qc * 2;
    #pragma unroll
    for (int n = 0; n < 4; n++) {
        int col = wn * 32 + n * 8 + cpair;
        float b0 = __ldg(bias + col), b1 = __ldg(bias + col + 1);
        #pragma unroll
        for (int m = 0; m < 2; m++) {
            int r = wm * 32 + m * 16 + qr;
            os[r * MMPAD + col]           = acc[m][n][0] + b0;
            os[r * MMPAD + col + 1]       = acc[m][n][1] + b1;
            os[(r + 8) * MMPAD + col]     = acc[m][n][2] + b0;
            os[(r + 8) * MMPAD + col + 1] = acc[m][n][3] + b1;
        }
    }
    __syncthreads();

    float4 g = __ldg((const float4*)gamma + lane);
    float4 bb = __ldg((const float4*)beta + lane);
    for (int rr = wid; rr < 64; rr += 8) {
        int gr = m0 + rr;
        if (gr >= M) break;
        float4 v = *(const float4*)&os[rr * MMPAD + lane * 4];
        float s = v.x + v.y + v.z + v.w;
        #pragma unroll
        for (int off = 16; off; off >>= 1) s += __shfl_xor_sync(0xFFFFFFFFu, s, off);
        float mu = s * (1.0f / 128.0f);
        float dx = v.x - mu, dy = v.y - mu, dz = v.z - mu, dw = v.w - mu;
        float q = dx * dx + dy * dy + dz * dz + dw * dw;
        #pragma unroll
        for (int off = 16; off; off >>= 1) q += __shfl_xor_sync(0xFFFFFFFFu, q, off);
        float r = rsqrtf(q * (1.0f / 128.0f) + 1e-5f);
        float4 o;
        o.x = dx * r * g.x + bb.x;
        o.y = dy * r * g.y + bb.y;
        o.z = dz * r * g.z + bb.z;
        o.w = dw * r * g.w + bb.w;
        if (sc != nullptr) {
            uint2 su = __ldg((const uint2*)(sc + (size_t)gr * D) + lane);
            float2 s0 = __half22float2(*(__half2*)&su.x);
            float2 s1 = __half22float2(*(__half2*)&su.y);
            o.x += s0.x; o.y += s0.y; o.z += s1.x; o.w += s1.y;
        }
        o.x = gelu_f(o.x); o.y = gelu_f(o.y); o.z = gelu_f(o.z); o.w = gelu_f(o.w);
        if (OUT_HALF) {
            __half* oh = (__half*)outp;
            uint2 u;
            u.x = f2h2(o.x, o.y);
            u.y = f2h2(o.z, o.w);
            *((uint2*)(oh + (size_t)gr * D) + lane) = u;
        } else {
            float* of = (float*)outp;
            *(float4*)(of + (size_t)gr * D + lane * 4) = o;
        }
    }
}

extern "C" void kernel_launch(void* const* d_in, const int* in_sizes, int n_in,
                              void* d_out, int out_size) {
    const float* x     = (const float*)d_in[0];
    const int*   edges = (const int*)  d_in[1];
    const float* dp_w  = (const float*)d_in[2];
    const float* dp_b  = (const float*)d_in[3];
    const float* sc_w  = (const float*)d_in[4];
    const float* sc_b  = (const float*)d_in[5];
    const float* g1_lw = (const float*)d_in[6];
    const float* g1_lb = (const float*)d_in[7];
    const float* g1_rw = (const float*)d_in[8];
    const float* n1_g  = (const float*)d_in[9];
    const float* n1_b  = (const float*)d_in[10];
    const float* g2_lw = (const float*)d_in[11];
    const float* g2_lb = (const float*)d_in[12];
    const float* g2_rw = (const float*)d_in[13];
    const float* n2_g  = (const float*)d_in[14];
    const float* n2_b  = (const float*)d_in[15];
    float* out = (float*)d_out;

    int M = in_sizes[0] / D;      // 50000
    int E = in_sizes[1] / 2;      // 640000
    const int* srcp = edges;
    const int* dstp = edges + E;

    __half *h0, *shrt, *meanb, *tb, *w16, *w16b;
    cudaGetSymbolAddress((void**)&h0,    g_h0);
    cudaGetSymbolAddress((void**)&shrt,  g_short);
    cudaGetSymbolAddress((void**)&meanb, g_mean);
    cudaGetSymbolAddress((void**)&tb,    g_t);
    cudaGetSymbolAddress((void**)&w16,   g_w16);
    cudaGetSymbolAddress((void**)&w16b,  g_w16b);
    __half* dpw_h  = w16 + 0 * D * D;
    __half* scw_h  = w16 + 1 * D * D;
    __half* g1lw_h = w16 + 2 * D * D;
    __half* g1rw_h = w16 + 3 * D * D;
    __half* g2lw_h = w16b + 0 * D * D;
    __half* g2rw_h = w16b + 1 * D * D;

    const int MM_SMEM = (64 + 128) * KPAD * (int)sizeof(__half);  // 52224 B
    cudaFuncSetAttribute(mm_dual_kernel, cudaFuncAttributeMaxDynamicSharedMemorySize, MM_SMEM);
    cudaFuncSetAttribute(mm_sage_kernel<true>,  cudaFuncAttributeMaxDynamicSharedMemorySize, MM_SMEM);
    cudaFuncSetAttribute(mm_sage_kernel<false>, cudaFuncAttributeMaxDynamicSharedMemorySize, MM_SMEM);

    int nblk = (M + 63) / 64;
    int wgrid = (M * 32 + 255) / 256;
    int nb256 = (M + 255) / 256;
    int egrid4 = (E + 1023) / 1024;

    cudaStream_t side = g_fork.side;

    // ---- fork: CSR build on side stream, concurrent with wconv + mm_dual ----
    cudaEventRecord(g_fork.evFork, 0);
    cudaStreamWaitEvent(side, g_fork.evFork, 0);

    zero2_kernel<<<nb256, 256, 0, side>>>(M);
    hist_kernel<<<egrid4, 256, 0, side>>>(dstp, E);
    scan_lookback_kernel<<<nb256, 256, 0, side>>>(M);
    fill_kernel<<<egrid4, 256, 0, side>>>(srcp, dstp, E);
    cudaEventRecord(g_fork.evJoin, side);

    // ---- main branch: weights -> fp16, then h0/shortcut GEMM ----
    wconv_kernel<<<192, 256>>>(dp_w, sc_w, g1_lw, g1_rw, g2_lw, g2_rw);
    mm_dual_kernel<<<nblk, 256, MM_SMEM>>>(x, dpw_h, dp_b, scw_h, sc_b, h0, shrt, M);

    // ---- join: aggregation needs both CSR and h0 ----
    cudaStreamWaitEvent(0, g_fork.evJoin, 0);

    // SAGE 1 + LN + GELU fused -> h1 (fp16)
    agg_kernel<<<wgrid, 256>>>(h0, meanb, M);
    mm_sage_kernel<true><<<nblk, 256, MM_SMEM>>>(meanb, g1lw_h, h0, g1rw_h, g1_lb,
                                                 n1_g, n1_b, nullptr, tb, M);

    // SAGE 2 + LN + shortcut + GELU fused -> out (fp32)
    agg_kernel<<<wgrid, 256>>>(tb, meanb, M);
    mm_sage_kernel<false><<<nblk, 256, MM_SMEM>>>(meanb, g2lw_h, tb, g2rw_h, g2_lb,
                                                  n2_g, n2_b, shrt, out, M);
}

// round 17
// speedup vs baseline: 1.1876x; 1.0176x over previous
#include <cuda_runtime.h>
#include <cuda_fp16.h>
#include <math.h>

#define D 128
#define NN 50000
#define NE 640000
#define MMPAD 132
#define KPAD 136   // halves per row in fp16 staging (128 + 8 pad)

// ---- scratch (device globals: allocation-free) ----
// g_deg / g_desc invariant: zero at kernel_launch entry. Zero-initialized at
// module load; fill_kernel re-zeros them at the end of every launch (after
// scan has consumed them), so every graph replay re-establishes the invariant.
__device__ __half g_h0[NN * D];     // h0 (fp16)
__device__ __half g_short[NN * D];  // shortcut (fp16)
__device__ __half g_mean[NN * D];   // mean aggregation buffer (fp16)
__device__ __half g_t[NN * D];      // h1 (fp16)
__device__ __half g_w16[4][D * D];  // fp16 weights: dp_w, sc_w, g1_lw, g1_rw
__device__ __half g_w16b[2][D * D]; // fp16 weights: g2_lw, g2_rw
__device__ int    g_deg[NN];
__device__ int    g_cursor[NN];
__device__ int    g_rp[NN + 1];
__device__ int    g_col[NE];
__device__ unsigned long long g_desc[64];    // lookback descriptors (49 blocks used)

// ---- host-side stream/event for forked graph capture (host objects, not device mem) ----
struct ForkCtx {
    cudaStream_t side;
    cudaEvent_t evFork, evJoin;
    ForkCtx() {
        cudaStreamCreateWithFlags(&side, cudaStreamNonBlocking);
        cudaEventCreateWithFlags(&evFork, cudaEventDisableTiming);
        cudaEventCreateWithFlags(&evJoin, cudaEventDisableTiming);
    }
};
static ForkCtx g_fork;

__device__ __forceinline__ float gelu_f(float x) {
    return 0.5f * x * (1.0f + erff(x * 0.70710678118654752f));
}

__device__ __forceinline__ unsigned f2h2(float a, float b) {
    __half2 h = __floats2half2_rn(a, b);
    return *(unsigned*)&h;
}

__device__ __forceinline__ void mma_f16(float* c, const unsigned* a, const unsigned* b) {
    asm volatile(
        "mma.sync.aligned.m16n8k16.row.col.f32.f16.f16.f32 "
        "{%0,%1,%2,%3},{%4,%5,%6,%7},{%8,%9},{%0,%1,%2,%3};"
        : "+f"(c[0]), "+f"(c[1]), "+f"(c[2]), "+f"(c[3])
        : "r"(a[0]), "r"(a[1]), "r"(a[2]), "r"(a[3]), "r"(b[0]), "r"(b[1]));
}

__device__ __forceinline__ void ldsm_x4(unsigned* r, unsigned addr) {
    asm volatile("ldmatrix.sync.aligned.m8n8.x4.shared.b16 {%0,%1,%2,%3}, [%4];"
        : "=r"(r[0]), "=r"(r[1]), "=r"(r[2]), "=r"(r[3]) : "r"(addr));
}

__device__ __forceinline__ unsigned ldsm_a_addr(const __half* as, int ar, int lane) {
    return (unsigned)__cvta_generic_to_shared(
        &as[(ar + (lane & 15)) * KPAD + ((lane >> 4) * 8)]);
}
__device__ __forceinline__ unsigned ldsm_b_addr(const __half* ws, int nb, int lane) {
    return (unsigned)__cvta_generic_to_shared(
        &ws[(nb + ((lane >> 4) * 8) + (lane & 7)) * KPAD + (((lane >> 3) & 1) * 8)]);
}

// ---------------- one-time weight fp32 -> fp16 conversion ----------------
__global__ void wconv_kernel(const float* __restrict__ w0, const float* __restrict__ w1,
                             const float* __restrict__ w2, const float* __restrict__ w3,
                             const float* __restrict__ w4, const float* __restrict__ w5) {
    int mat = blockIdx.x >> 5;
    int off = (((blockIdx.x & 31) * 256) + threadIdx.x) * 2;
    const float* src;
    __half* dst;
    switch (mat) {
        case 0:  src = w0; dst = g_w16[0];  break;
        case 1:  src = w1; dst = g_w16[1];  break;
        case 2:  src = w2; dst = g_w16[2];  break;
        case 3:  src = w3; dst = g_w16[3];  break;
        case 4:  src = w4; dst = g_w16b[0]; break;
        default: src = w5; dst = g_w16b[1]; break;
    }
    float2 v = *(const float2*)(src + off);
    *(unsigned*)(dst + off) = f2h2(v.x, v.y);
}

// ---------------- CSR build ----------------
__global__ void hist_kernel(const int* __restrict__ dst, int e_cnt) {
    int base = (blockIdx.x * blockDim.x + threadIdx.x) * 4;
    if (base + 4 <= e_cnt) {
        int4 d = *(const int4*)(dst + base);
        atomicAdd(&g_deg[d.x], 1);
        atomicAdd(&g_deg[d.y], 1);
        atomicAdd(&g_deg[d.z], 1);
        atomicAdd(&g_deg[d.w], 1);
    } else {
        for (int j = 0; j < 4; j++)
            if (base + j < e_cnt) atomicAdd(&g_deg[dst[base + j]], 1);
    }
}

// single-pass scan, 1024-thread blocks (49 blocks), warp-parallel decoupled lookback
__global__ __launch_bounds__(1024)
void scan_lookback_kernel(int n) {
    __shared__ int wsum[32];
    __shared__ int s_total;
    __shared__ int s_excl;
    int tid = threadIdx.x, lane = tid & 31, wid = tid >> 5;
    int bid = blockIdx.x;
    int i = bid * 1024 + tid;
    int v = (i < n) ? g_deg[i] : 0;
    int x = v;
    #pragma unroll
    for (int off = 1; off < 32; off <<= 1) {
        int t = __shfl_up_sync(0xFFFFFFFFu, x, off);
        if (lane >= off) x += t;
    }
    if (lane == 31) wsum[wid] = x;
    __syncthreads();
    if (tid < 32) {
        int w = wsum[tid];
        #pragma unroll
        for (int off = 1; off < 32; off <<= 1) {
            int t = __shfl_up_sync(0xFFFFFFFFu, w, off);
            if (tid >= off) w += t;
        }
        wsum[tid] = w;
    }
    __syncthreads();
    int incl = x + ((wid > 0) ? wsum[wid - 1] : 0);
    if (tid == 1023) { s_total = incl; }
    __syncthreads();
    int total = s_total;

    if (tid == 0) {
        __threadfence();
        unsigned long long st = (bid == 0) ? (2ULL << 32) : (1ULL << 32);
        atomicExch(&g_desc[bid], st | (unsigned)total);
        if (bid == 0) s_excl = 0;
    }
    if (bid > 0 && wid == 0) {
        int j = bid - 1 - lane;
        long ex = 0;
        while (true) {
            unsigned long long d;
            unsigned st;
            if (j >= 0) {
                do { d = atomicAdd(&g_desc[j], 0ULL); st = (unsigned)(d >> 32); } while (st == 0);
            } else {
                d = (2ULL << 32); st = 2u;
            }
            unsigned mask = __ballot_sync(0xFFFFFFFFu, st == 2u);
            if (mask) {
                int firstP = __ffs(mask) - 1;
                unsigned contrib = (lane <= firstP) ? (unsigned)d : 0u;
                #pragma unroll
                for (int off = 16; off; off >>= 1)
                    contrib += __shfl_xor_sync(0xFFFFFFFFu, contrib, off);
                ex += (long)contrib;
                break;
            } else {
                unsigned contrib = (unsigned)d;
                #pragma unroll
                for (int off = 16; off; off >>= 1)
                    contrib += __shfl_xor_sync(0xFFFFFFFFu, contrib, off);
                ex += (long)contrib;
                j -= 32;
            }
        }
        if (lane == 0) {
            __threadfence();
            atomicExch(&g_desc[bid], (2ULL << 32) | (unsigned)(ex + total));
            s_excl = (int)ex;
        }
    }
    __syncthreads();
    int off = s_excl;
    if (i < n) {
        int gincl = incl + off;
        g_rp[i + 1] = gincl;
        g_cursor[i] = gincl - v;
    }
    if (i == 0) g_rp[0] = 0;
}

__global__ void fill_kernel(const int* __restrict__ src, const int* __restrict__ dst, int e_cnt) {
    int base = (blockIdx.x * blockDim.x + threadIdx.x) * 4;
    if (base + 4 <= e_cnt) {
        int4 s = *(const int4*)(src + base);
        int4 d = *(const int4*)(dst + base);
        g_col[atomicAdd(&g_cursor[d.x], 1)] = s.x;
        g_col[atomicAdd(&g_cursor[d.y], 1)] = s.y;
        g_col[atomicAdd(&g_cursor[d.z], 1)] = s.z;
        g_col[atomicAdd(&g_cursor[d.w], 1)] = s.w;
    } else {
        for (int j = 0; j < 4; j++)
            if (base + j < e_cnt) {
                int dd = dst[base + j];
                int p = atomicAdd(&g_cursor[dd], 1);
                g_col[p] = src[base + j];
            }
    }
    // re-zero deg/desc for the next replay (scan already consumed them this launch)
    int t = blockIdx.x * blockDim.x + threadIdx.x;
    int stride = gridDim.x * blockDim.x;
    for (int k = t; k < NN; k += stride) g_deg[k] = 0;
    if (t < 64) g_desc[t] = 0ULL;
}

// ---------------- mean aggregation: warp per destination node (fp16 rows) ----------------
// Unroll-by-4 software pipeline; accumulation order strictly sequential
// (i, i+1, i+2, i+3) -> bit-identical to the serial loop.
__global__ void agg_kernel(const __half* __restrict__ h, __half* __restrict__ meanout, int n) {
    int w = (int)((blockIdx.x * blockDim.x + threadIdx.x) >> 5);
    int lane = threadIdx.x & 31;
    if (w >= n) return;
    int s = g_rp[w], e = g_rp[w + 1];
    float a0 = 0.f, a1 = 0.f, a2 = 0.f, a3 = 0.f;
    int i = s;
    for (; i + 4 <= e; i += 4) {
        int c0 = __ldg(&g_col[i]);
        int c1 = __ldg(&g_col[i + 1]);
        int c2 = __ldg(&g_col[i + 2]);
        int c3 = __ldg(&g_col[i + 3]);
        uint2 u0 = __ldg((const uint2*)(h + (size_t)c0 * D) + lane);
        uint2 u1 = __ldg((const uint2*)(h + (size_t)c1 * D) + lane);
        uint2 u2 = __ldg((const uint2*)(h + (size_t)c2 * D) + lane);
        uint2 u3 = __ldg((const uint2*)(h + (size_t)c3 * D) + lane);
        float2 f0, f1;
        f0 = __half22float2(*(__half2*)&u0.x); f1 = __half22float2(*(__half2*)&u0.y);
        a0 += f0.x; a1 += f0.y; a2 += f1.x; a3 += f1.y;
        f0 = __half22float2(*(__half2*)&u1.x); f1 = __half22float2(*(__half2*)&u1.y);
        a0 += f0.x; a1 += f0.y; a2 += f1.x; a3 += f1.y;
        f0 = __half22float2(*(__half2*)&u2.x); f1 = __half22float2(*(__half2*)&u2.y);
        a0 += f0.x; a1 += f0.y; a2 += f1.x; a3 += f1.y;
        f0 = __half22float2(*(__half2*)&u3.x); f1 = __half22float2(*(__half2*)&u3.y);
        a0 += f0.x; a1 += f0.y; a2 += f1.x; a3 += f1.y;
    }
    for (; i < e; i++) {
        int c0 = __ldg(&g_col[i]);
        uint2 u0 = __ldg((const uint2*)(h + (size_t)c0 * D) + lane);
        float2 f0 = __half22float2(*(__half2*)&u0.x);
        float2 f1 = __half22float2(*(__half2*)&u0.y);
        a0 += f0.x; a1 += f0.y; a2 += f1.x; a3 += f1.y;
    }
    float inv = 1.0f / (float)max(e - s, 1);
    uint2 o;
    o.x = f2h2(a0 * inv, a1 * inv);
    o.y = f2h2(a2 * inv, a3 * inv);
    *((uint2*)(meanout + (size_t)w * D) + lane) = o;
}

// ---------------- staging helpers ----------------
__device__ __forceinline__ void stage_A(__half* as, const float* A, int m0, int M, int tid) {
    #pragma unroll
    for (int i = 0; i < 8; i++) {
        int idx = tid + i * 256;
        int row = idx >> 5;
        int c4  = (idx & 31) * 4;
        int gm = m0 + row;
        float4 v = (gm < M) ? __ldg((const float4*)(A + (size_t)gm * D + c4))
                            : make_float4(0.f, 0.f, 0.f, 0.f);
        uint2 u = make_uint2(f2h2(v.x, v.y), f2h2(v.z, v.w));
        *(uint2*)(&as[row * KPAD + c4]) = u;
    }
}
__device__ __forceinline__ void stage_Ah(__half* as, const __half* A, int m0, int M, int tid) {
    #pragma unroll
    for (int i = 0; i < 4; i++) {
        int idx = tid + i * 256;
        int row = idx >> 4;
        int c8  = (idx & 15) * 8;
        int gm = m0 + row;
        uint4 u = (gm < M) ? __ldg((const uint4*)(A + (size_t)gm * D + c8))
                           : make_uint4(0u, 0u, 0u, 0u);
        *(uint4*)(&as[row * KPAD + c8]) = u;
    }
}
__device__ __forceinline__ void stage_Wh(__half* ws, const __half* W, int tid) {
    #pragma unroll
    for (int i = 0; i < 8; i++) {
        int idx = tid + i * 256;
        int row = idx >> 4;
        int c8  = (idx & 15) * 8;
        uint4 u = __ldg((const uint4*)(W + (size_t)row * D + c8));
        *(uint4*)(&ws[row * KPAD + c8]) = u;
    }
}

// ---------------- mm_dual: out0(h0,fp16) = gelu(A@W0^T+b0), out1(shortcut,fp16) = A@W1^T+b1 ----------------
__global__ __launch_bounds__(256, 2)
void mm_dual_kernel(const float* __restrict__ A,
                    const __half* __restrict__ W0, const float* __restrict__ b0v,
                    const __half* __restrict__ W1, const float* __restrict__ b1v,
                    __half* __restrict__ out0, __half* __restrict__ out1, int M) {
    extern __shared__ __half smemh[];
    __half* as = smemh;
    __half* ws = smemh + 64 * KPAD;
    int tid = threadIdx.x, lane = tid & 31, wid = tid >> 5;
    int wm = wid & 1, wn = wid >> 1;
    int m0 = blockIdx.x * 64;
    int qr = lane >> 2, qc = lane & 3;

    unsigned aaddr0 = ldsm_a_addr(as, wm * 32, lane);
    unsigned aaddr1 = aaddr0 + 16 * KPAD * 2;
    unsigned baddr0 = ldsm_b_addr(ws, wn * 32, lane);
    unsigned baddr1 = baddr0 + 16 * KPAD * 2;

    float acc[2][2][4][4];
    #pragma unroll
    for (int w = 0; w < 2; w++)
        #pragma unroll
        for (int i = 0; i < 2; i++)
            #pragma unroll
            for (int j = 0; j < 4; j++)
                #pragma unroll
                for (int k = 0; k < 4; k++) acc[w][i][j][k] = 0.f;

    stage_A(as, A, m0, M, tid);
    #pragma unroll
    for (int w = 0; w < 2; w++) {
        if (w) __syncthreads();
        stage_Wh(ws, w ? W1 : W0, tid);
        __syncthreads();
        #pragma unroll
        for (int ks = 0; ks < 8; ks++) {
            unsigned koff = ks * 32;
            unsigned afr[2][4], bfr[8];
            ldsm_x4(afr[0], aaddr0 + koff);
            ldsm_x4(afr[1], aaddr1 + koff);
            ldsm_x4(&bfr[0], baddr0 + koff);
            ldsm_x4(&bfr[4], baddr1 + koff);
            #pragma unroll
            for (int m = 0; m < 2; m++)
                #pragma unroll
                for (int n = 0; n < 4; n++)
                    mma_f16(acc[w][m][n], afr[m], &bfr[2 * n]);
        }
    }

    int cpair = qc * 2;
    #pragma unroll
    for (int n = 0; n < 4; n++) {
        int col = wn * 32 + n * 8 + cpair;
        float b00 = __ldg(b0v + col), b01 = __ldg(b0v + col + 1);
        float b10 = __ldg(b1v + col), b11 = __ldg(b1v + col + 1);
        #pragma unroll
        for (int m = 0; m < 2; m++) {
            int gr = m0 + wm * 32 + m * 16 + qr;
            if (gr < M) {
                *(unsigned*)(out0 + (size_t)gr * D + col) =
                    f2h2(gelu_f(acc[0][m][n][0] + b00), gelu_f(acc[0][m][n][1] + b01));
                *(unsigned*)(out1 + (size_t)gr * D + col) =
                    f2h2(acc[1][m][n][0] + b10, acc[1][m][n][1] + b11);
            }
            if (gr + 8 < M) {
                *(unsigned*)(out0 + (size_t)(gr + 8) * D + col) =
                    f2h2(gelu_f(acc[0][m][n][2] + b00), gelu_f(acc[0][m][n][3] + b01));
                *(unsigned*)(out1 + (size_t)(gr + 8) * D + col) =
                    f2h2(acc[1][m][n][2] + b10, acc[1][m][n][3] + b11);
            }
        }
    }
}

// ---------------- mm_sage: out = gelu( LN( A0@W0^T + A1@W1^T + bias ) [+ sc] ) ----------------
template <bool OUT_HALF>
__global__ __launch_bounds__(256, 3)
void mm_sage_kernel(const __half* __restrict__ A0, const __half* __restrict__ W0,
                    const __half* __restrict__ A1, const __half* __restrict__ W1,
                    const float* __restrict__ bias,
                    const float* __restrict__ gamma, const float* __restrict__ beta,
                    const __half* __restrict__ sc,
                    void* __restrict__ outp, int M) {
    extern __shared__ __half smemh[];
    __half* as = smemh;
    __half* ws = smemh + 64 * KPAD;
    int tid = threadIdx.x, lane = tid & 31, wid = tid >> 5;
    int wm = wid & 1, wn = wid >> 1;
    int m0 = blockIdx.x * 64;
    int qr = lane >> 2, qc = lane & 3;

    unsigned aaddr0 = ldsm_a_addr(as, wm * 32, lane);
    unsigned aaddr1 = aaddr0 + 16 * KPAD * 2;
    unsigned baddr0 = ldsm_b_addr(ws, wn * 32, lane);
    unsigned baddr1 = baddr0 + 16 * KPAD * 2;

    float acc[2][4][4];
    #pragma unroll
    for (int i = 0; i < 2; i++)
        #pragma unroll
        for (int j = 0; j < 4; j++)
            #pragma unroll
            for (int k = 0; k < 4; k++) acc[i][j][k] = 0.f;

    #pragma unroll
    for (int ph = 0; ph < 2; ph++) {
        if (ph) __syncthreads();
        stage_Ah(as, ph ? A1 : A0, m0, M, tid);
        stage_Wh(ws, ph ? W1 : W0, tid);
        __syncthreads();
        #pragma unroll
        for (int ks = 0; ks < 8; ks++) {
            unsigned koff = ks * 32;
            unsigned afr[2][4], bfr[8];
            ldsm_x4(afr[0], aaddr0 + koff);
            ldsm_x4(afr[1], aaddr1 + koff);
            ldsm_x4(&bfr[0], baddr0 + koff);
            ldsm_x4(&bfr[4], baddr1 + koff);
            #pragma unroll
            for (int m = 0; m < 2; m++)
                #pragma unroll
                for (int n = 0; n < 4; n++)
                    mma_f16(acc[m][n], afr[m], &bfr[2 * n]);
        }
    }

    // spill tile (+bias) to smem as fp32, then warp-per-row LN epilogue
    float* os = (float*)smemh;   // reuse, [64][MMPAD] fp32
    __syncthreads();
    int cpair = qc * 2;
    #pragma unroll
    for (int n = 0; n < 4; n++) {
        int col = wn * 32 + n * 8 + cpair;
        float b0 = __ldg(bias + col), b1 = __ldg(bias + col + 1);
        #pragma unroll
        for (int m = 0; m < 2; m++) {
            int r = wm * 32 + m * 16 + qr;
            os[r * MMPAD + col]           = acc[m][n][0] + b0;
            os[r * MMPAD + col + 1]       = acc[m][n][1] + b1;
            os[(r + 8) * MMPAD + col]     = acc[m][n][2] + b0;
            os[(r + 8) * MMPAD + col + 1] = acc[m][n][3] + b1;
        }
    }
    __syncthreads();

    float4 g = __ldg((const float4*)gamma + lane);
    float4 bb = __ldg((const float4*)beta + lane);
    for (int rr = wid; rr < 64; rr += 8) {
        int gr = m0 + rr;
        if (gr >= M) break;
        float4 v = *(const float4*)&os[rr * MMPAD + lane * 4];
        float s = v.x + v.y + v.z + v.w;
        #pragma unroll
        for (int off = 16; off; off >>= 1) s += __shfl_xor_sync(0xFFFFFFFFu, s, off);
        float mu = s * (1.0f / 128.0f);
        float dx = v.x - mu, dy = v.y - mu, dz = v.z - mu, dw = v.w - mu;
        float q = dx * dx + dy * dy + dz * dz + dw * dw;
        #pragma unroll
        for (int off = 16; off; off >>= 1) q += __shfl_xor_sync(0xFFFFFFFFu, q, off);
        float r = rsqrtf(q * (1.0f / 128.0f) + 1e-5f);
        float4 o;
        o.x = dx * r * g.x + bb.x;
        o.y = dy * r * g.y + bb.y;
        o.z = dz * r * g.z + bb.z;
        o.w = dw * r * g.w + bb.w;
        if (sc != nullptr) {
            uint2 su = __ldg((const uint2*)(sc + (size_t)gr * D) + lane);
            float2 s0 = __half22float2(*(__half2*)&su.x);
            float2 s1 = __half22float2(*(__half2*)&su.y);
            o.x += s0.x; o.y += s0.y; o.z += s1.x; o.w += s1.y;
        }
        o.x = gelu_f(o.x); o.y = gelu_f(o.y); o.z = gelu_f(o.z); o.w = gelu_f(o.w);
        if (OUT_HALF) {
            __half* oh = (__half*)outp;
            uint2 u;
            u.x = f2h2(o.x, o.y);
            u.y = f2h2(o.z, o.w);
            *((uint2*)(oh + (size_t)gr * D) + lane) = u;
        } else {
            float* of = (float*)outp;
            *(float4*)(of + (size_t)gr * D + lane * 4) = o;
        }
    }
}

extern "C" void kernel_launch(void* const* d_in, const int* in_sizes, int n_in,
                              void* d_out, int out_size) {
    const float* x     = (const float*)d_in[0];
    const int*   edges = (const int*)  d_in[1];
    const float* dp_w  = (const float*)d_in[2];
    const float* dp_b  = (const float*)d_in[3];
    const float* sc_w  = (const float*)d_in[4];
    const float* sc_b  = (const float*)d_in[5];
    const float* g1_lw = (const float*)d_in[6];
    const float* g1_lb = (const float*)d_in[7];
    const float* g1_rw = (const float*)d_in[8];
    const float* n1_g  = (const float*)d_in[9];
    const float* n1_b  = (const float*)d_in[10];
    const float* g2_lw = (const float*)d_in[11];
    const float* g2_lb = (const float*)d_in[12];
    const float* g2_rw = (const float*)d_in[13];
    const float* n2_g  = (const float*)d_in[14];
    const float* n2_b  = (const float*)d_in[15];
    float* out = (float*)d_out;

    int M = in_sizes[0] / D;      // 50000
    int E = in_sizes[1] / 2;      // 640000
    const int* srcp = edges;
    const int* dstp = edges + E;

    __half *h0, *shrt, *meanb, *tb, *w16, *w16b;
    cudaGetSymbolAddress((void**)&h0,    g_h0);
    cudaGetSymbolAddress((void**)&shrt,  g_short);
    cudaGetSymbolAddress((void**)&meanb, g_mean);
    cudaGetSymbolAddress((void**)&tb,    g_t);
    cudaGetSymbolAddress((void**)&w16,   g_w16);
    cudaGetSymbolAddress((void**)&w16b,  g_w16b);
    __half* dpw_h  = w16 + 0 * D * D;
    __half* scw_h  = w16 + 1 * D * D;
    __half* g1lw_h = w16 + 2 * D * D;
    __half* g1rw_h = w16 + 3 * D * D;
    __half* g2lw_h = w16b + 0 * D * D;
    __half* g2rw_h = w16b + 1 * D * D;

    const int MM_SMEM = (64 + 128) * KPAD * (int)sizeof(__half);  // 52224 B
    cudaFuncSetAttribute(mm_dual_kernel, cudaFuncAttributeMaxDynamicSharedMemorySize, MM_SMEM);
    cudaFuncSetAttribute(mm_sage_kernel<true>,  cudaFuncAttributeMaxDynamicSharedMemorySize, MM_SMEM);
    cudaFuncSetAttribute(mm_sage_kernel<false>, cudaFuncAttributeMaxDynamicSharedMemorySize, MM_SMEM);

    int nblk = (M + 63) / 64;
    int wgrid = (M * 32 + 255) / 256;
    int nb1024 = (M + 1023) / 1024;   // 49 blocks
    int egrid4 = (E + 1023) / 1024;

    cudaStream_t side = g_fork.side;

    // ---- fork: CSR build on side stream, concurrent with wconv + mm_dual ----
    // (g_deg/g_desc are zero at entry: module-load init, then re-zeroed by
    //  fill_kernel at the end of every launch)
    cudaEventRecord(g_fork.evFork, 0);
    cudaStreamWaitEvent(side, g_fork.evFork, 0);

    hist_kernel<<<egrid4, 256, 0, side>>>(dstp, E);
    scan_lookback_kernel<<<nb1024, 1024, 0, side>>>(M);
    fill_kernel<<<egrid4, 256, 0, side>>>(srcp, dstp, E);
    cudaEventRecord(g_fork.evJoin, side);

    // ---- main branch: weights -> fp16, then h0/shortcut GEMM ----
    wconv_kernel<<<192, 256>>>(dp_w, sc_w, g1_lw, g1_rw, g2_lw, g2_rw);
    mm_dual_kernel<<<nblk, 256, MM_SMEM>>>(x, dpw_h, dp_b, scw_h, sc_b, h0, shrt, M);

    // ---- join: aggregation needs both CSR and h0 ----
    cudaStreamWaitEvent(0, g_fork.evJoin, 0);

    // SAGE 1 + LN + GELU fused -> h1 (fp16)
    agg_kernel<<<wgrid, 256>>>(h0, meanb, M);
    mm_sage_kernel<true><<<nblk, 256, MM_SMEM>>>(meanb, g1lw_h, h0, g1rw_h, g1_lb,
                                                 n1_g, n1_b, nullptr, tb, M);

    // SAGE 2 + LN + shortcut + GELU fused -> out (fp32)
    agg_kernel<<<wgrid, 256>>>(tb, meanb, M);
    mm_sage_kernel<false><<<nblk, 256, MM_SMEM>>>(meanb, g2lw_h, tb, g2rw_h, g2_lb,
                                                  n2_g, n2_b, shrt, out, M);
}